// round 13
// baseline (speedup 1.0000x reference)
#include <cuda_runtime.h>
#include <cuda_fp16.h>
#include <cstdint>

#define K_DIM 7168
#define N_DIM 256
#define BM 128
#define BK 128
#define NKB (K_DIM / BK)       // 56
#define THREADS 512

#define XSTR 528               // x smem row stride bytes (128 f32 + 16B pad)
#define ARS 144                // A fp8 row stride bytes (128 + 16 pad)
#define BRS 144                // B fp8 row stride bytes
#define A_ST (128 * ARS)       // 18432 per stage
#define B_ST (256 * BRS)       // 36864 per stage

// smem offsets
#define OFF_WS 0               // 112 floats ws copy (448B, pad to 512)
#define OFF_SC 512             // 2 stages x 128 f32 act scales (1024B)
#define OFF_X  1536            // 67584B x staging (single buffer)
#define OFF_A  69120           // 2 x A_ST
#define OFF_B  105984          // 2 x B_ST
#define SMEM_BYTES 179712

// fp8 weight bytes, [n][k] layout (k contiguous)
__device__ __align__(16) uint8_t g_w8[(size_t)N_DIM * K_DIM];

// ---------------- helpers ----------------

// pack two floats (already scaled by inv) to two e4m3 bytes; low byte = a
__device__ __forceinline__ uint32_t q2(float a, float b, float inv) {
    uint16_t p;
    asm("cvt.rn.satfinite.e4m3x2.f32 %0, %1, %2;"
        : "=h"(p) : "f"(b * inv), "f"(a * inv));
    return (uint32_t)p;
}

__device__ __forceinline__ void qmma(float* c, const uint32_t* a,
                                     uint32_t b0, uint32_t b1) {
    asm volatile(
        "mma.sync.aligned.m16n8k32.row.col.f32.e4m3.e4m3.f32 "
        "{%0,%1,%2,%3}, {%4,%5,%6,%7}, {%8,%9}, {%0,%1,%2,%3};"
        : "+f"(c[0]), "+f"(c[1]), "+f"(c[2]), "+f"(c[3])
        : "r"(a[0]), "r"(a[1]), "r"(a[2]), "r"(a[3]), "r"(b0), "r"(b1));
}

#define LDSM4(r0, r1, r2, r3, addr)                                        \
    asm volatile("ldmatrix.sync.aligned.m8n8.x4.shared.b16 {%0,%1,%2,%3}, [%4];" \
                 : "=r"(r0), "=r"(r1), "=r"(r2), "=r"(r3) : "r"(addr))

#define CPA16(dst, src)                                                    \
    asm volatile("cp.async.cg.shared.global [%0], [%1], 16;"               \
                 :: "r"(dst), "l"(src))

// ---------------- prep: detect dtype + emit fp8 bytes [n][k] ----------------
// Every block samples the SAME first 4KB as f32: if the harness upcast the fp8
// weight to f32, all values are finite with |v|<1; if the buffer is raw fp8
// bytes, reassembled f32s have random exponents (P(all<1) ~ 2^-1000). All
// blocks reach identical verdicts deterministically.
__global__ void LinearDSV3_prep(const void* __restrict__ w) {
    float4 probe = ((const float4*)w)[threadIdx.x];   // first 4KB, in-bounds both ways
    int ok = (fabsf(probe.x) < 1.0f) && (fabsf(probe.y) < 1.0f) &&
             (fabsf(probe.z) < 1.0f) && (fabsf(probe.w) < 1.0f);
    ok = __syncthreads_and(ok);

    int idx4 = blockIdx.x * 256 + threadIdx.x;        // 4 elements per thread
    uint32_t packed;
    if (ok) {   // f32 buffer holding exact fp8 values: requantize exactly
        float4 v = ((const float4*)w)[idx4];
        uint16_t lo, hi;
        asm("cvt.rn.satfinite.e4m3x2.f32 %0, %1, %2;" : "=h"(lo) : "f"(v.y), "f"(v.x));
        asm("cvt.rn.satfinite.e4m3x2.f32 %0, %1, %2;" : "=h"(hi) : "f"(v.w), "f"(v.z));
        packed = (uint32_t)lo | ((uint32_t)hi << 16);
    } else {    // already raw fp8 bytes
        packed = ((const uint32_t*)w)[idx4];
    }
    ((uint32_t*)g_w8)[idx4] = packed;
}

// ---------------- main: fused act-quant + fp8 GEMM ----------------

__global__ __launch_bounds__(THREADS, 1) void LinearDSV3_gemm(
    const float* __restrict__ x, const float* __restrict__ ws,
    float* __restrict__ y) {
    extern __shared__ char smraw[];
    const uint32_t S  = (uint32_t)__cvta_generic_to_shared(smraw);
    const uint32_t Ws = S + OFF_WS;
    const uint32_t Sc = S + OFF_SC;
    const uint32_t Xb = S + OFF_X;
    const uint32_t Ab0 = S + OFF_A;
    const uint32_t Bb0 = S + OFF_B;

    const int t = threadIdx.x;
    const int lane = t & 31;
    const int wid = t >> 5;
    const int wm = wid & 3;          // 4 M-warps x 32 rows
    const int wn = wid >> 2;         // 4 N-warps x 64 cols
    const int m0 = blockIdx.x * BM;

    // quant mapping: 4 threads per row, 32 floats each
    const int lr = t >> 2;
    const int q  = t & 3;

    // copy weight scales (2 x 56) to smem
    if (t < 112) {
        float v = ws[t];
        asm volatile("st.shared.f32 [%0], %1;" :: "r"(Ws + t * 4), "f"(v));
    }

    // cp.async issuers
    auto issue_x = [&](int kb) {
#pragma unroll
        for (int j = 0; j < 8; ++j) {
            int c = t + j * THREADS;          // 0..4095
            int row = c >> 5;
            int u = c & 31;                    // logical 16B unit within row
            int phys = (u & 24) | ((u & 7) ^ ((u >> 3) & 3));   // bank swizzle
            uint32_t dst = Xb + (uint32_t)(row * XSTR + phys * 16);
            const void* src = x + (size_t)(m0 + row) * K_DIM + kb * BK + u * 4;
            CPA16(dst, src);
        }
    };
    auto issue_B = [&](int kb, uint32_t Bb) {
#pragma unroll
        for (int j = 0; j < 4; ++j) {
            int c = t + j * THREADS;          // 0..2047
            int n = c >> 3;
            int u = c & 7;
            uint32_t dst = Bb + (uint32_t)(n * BRS + u * 16);
            const void* src = g_w8 + (size_t)n * K_DIM + kb * BK + u * 16;
            CPA16(dst, src);
        }
    };

    // prologue: group 0 = {x(0), B(0)}
    issue_x(0);
    issue_B(0, Bb0);
    asm volatile("cp.async.commit_group;");

    float acc[2][8][4];
#pragma unroll
    for (int a = 0; a < 2; ++a)
#pragma unroll
        for (int b = 0; b < 8; ++b)
#pragma unroll
            for (int c = 0; c < 4; ++c) acc[a][b][c] = 0.0f;

    for (int kb = 0; kb < NKB; ++kb) {
        const int st = kb & 1;
        const uint32_t Ab = Ab0 + (uint32_t)st * A_ST;
        const uint32_t Bb = Bb0 + (uint32_t)st * B_ST;

        asm volatile("cp.async.wait_group 0;");
        __syncthreads();                       // x(kb), B(kb) visible to all

        // ---- act quant: read 32 f32 from x smem, write 32 fp8 to A smem ----
        float4 v[8];
        {
            const uint32_t xr = Xb + (uint32_t)(lr * XSTR);
#pragma unroll
            for (int j = 0; j < 8; ++j) {
                uint32_t addr = xr + (uint32_t)((8 * q + (j ^ q)) * 16);
                asm volatile("ld.shared.v4.f32 {%0,%1,%2,%3}, [%4];"
                             : "=f"(v[j].x), "=f"(v[j].y), "=f"(v[j].z), "=f"(v[j].w)
                             : "r"(addr));
            }
        }
        float am = 0.0f;
#pragma unroll
        for (int j = 0; j < 8; ++j) {
            am = fmaxf(am, fabsf(v[j].x)); am = fmaxf(am, fabsf(v[j].y));
            am = fmaxf(am, fabsf(v[j].z)); am = fmaxf(am, fabsf(v[j].w));
        }
        am = fmaxf(am, __shfl_xor_sync(0xFFFFFFFFu, am, 1));
        am = fmaxf(am, __shfl_xor_sync(0xFFFFFFFFu, am, 2));
        const float s = fmaxf(am, 1e-8f) / 448.0f;    // matches reference
        const float inv = 1.0f / s;

        uint32_t qo[8];
#pragma unroll
        for (int j = 0; j < 8; ++j)
            qo[j] = q2(v[j].x, v[j].y, inv) | (q2(v[j].z, v[j].w, inv) << 16);
        {
            uint32_t adst = Ab + (uint32_t)(lr * ARS + q * 32);
            asm volatile("st.shared.v4.b32 [%0], {%1,%2,%3,%4};"
                         :: "r"(adst), "r"(qo[0]), "r"(qo[1]), "r"(qo[2]), "r"(qo[3]));
            asm volatile("st.shared.v4.b32 [%0], {%1,%2,%3,%4};"
                         :: "r"(adst + 16), "r"(qo[4]), "r"(qo[5]), "r"(qo[6]), "r"(qo[7]));
        }
        if (q == 0)
            asm volatile("st.shared.f32 [%0], %1;"
                         :: "r"(Sc + (uint32_t)(st * 512 + lr * 4)), "f"(s));

        __syncthreads();                       // A(kb)+scales visible; x(kb) fully read

        // ---- issue next stage {x(kb+1), B(kb+1)} ----
        if (kb + 1 < NKB) {
            issue_x(kb + 1);
            issue_B(kb + 1, Bb0 + (uint32_t)((st ^ 1) * B_ST));
            asm volatile("cp.async.commit_group;");
        }

        // ---- fp8 MMA: block-accumulate, then scale into master ----
        float sw;
        asm volatile("ld.shared.f32 %0, [%1];"
                     : "=f"(sw) : "r"(Ws + (uint32_t)(((wn >> 1) * NKB + kb) * 4)));
        float sa[2][2];
#pragma unroll
        for (int mt = 0; mt < 2; ++mt) {
            uint32_t r0 = (uint32_t)(wm * 32 + mt * 16 + (lane >> 2));
            asm volatile("ld.shared.f32 %0, [%1];"
                         : "=f"(sa[mt][0]) : "r"(Sc + (uint32_t)st * 512 + r0 * 4));
            asm volatile("ld.shared.f32 %0, [%1];"
                         : "=f"(sa[mt][1]) : "r"(Sc + (uint32_t)st * 512 + (r0 + 8) * 4));
        }

        uint32_t af[32];   // [mt][ks][4]
        {
            const uint32_t ab = Ab + (uint32_t)((wm * 32 + (lane & 15)) * ARS
                                                + (lane >> 4) * 16);
#pragma unroll
            for (int mt = 0; mt < 2; ++mt)
#pragma unroll
                for (int ks = 0; ks < 4; ++ks) {
                    uint32_t* r = af + (mt * 4 + ks) * 4;
                    LDSM4(r[0], r[1], r[2], r[3],
                          ab + (uint32_t)(mt * 16 * ARS + ks * 32));
                }
        }

#pragma unroll
        for (int nt = 0; nt < 8; ++nt) {
            const uint32_t bb = Bb + (uint32_t)((wn * 64 + nt * 8 + (lane & 7)) * BRS
                                                + (lane >> 3) * 16);
            uint32_t b0, b1, b2, b3, b4, b5, b6, b7;
            LDSM4(b0, b1, b2, b3, bb);          // ks0: (b0,b1)  ks1: (b2,b3)
            LDSM4(b4, b5, b6, b7, bb + 64);     // ks2: (b4,b5)  ks3: (b6,b7)

            float t0[8] = {0, 0, 0, 0, 0, 0, 0, 0};
#pragma unroll
            for (int mt = 0; mt < 2; ++mt) {
                qmma(t0 + mt * 4, af + mt * 16 + 0,  b0, b1);
                qmma(t0 + mt * 4, af + mt * 16 + 4,  b2, b3);
                qmma(t0 + mt * 4, af + mt * 16 + 8,  b4, b5);
                qmma(t0 + mt * 4, af + mt * 16 + 12, b6, b7);
            }
#pragma unroll
            for (int mt = 0; mt < 2; ++mt) {
                float s0 = sa[mt][0] * sw, s1 = sa[mt][1] * sw;
                acc[mt][nt][0] += s0 * t0[mt * 4 + 0];
                acc[mt][nt][1] += s0 * t0[mt * 4 + 1];
                acc[mt][nt][2] += s1 * t0[mt * 4 + 2];
                acc[mt][nt][3] += s1 * t0[mt * 4 + 3];
            }
        }
    }

    // ---- epilogue ----
    const int mwb = m0 + wm * 32;
#pragma unroll
    for (int mt = 0; mt < 2; ++mt) {
        int r0 = mwb + mt * 16 + (lane >> 2);
#pragma unroll
        for (int nt = 0; nt < 8; ++nt) {
            int c = wn * 64 + nt * 8 + (lane & 3) * 2;
            float2 v0 = make_float2(acc[mt][nt][0], acc[mt][nt][1]);
            float2 v1 = make_float2(acc[mt][nt][2], acc[mt][nt][3]);
            *(float2*)(y + (size_t)r0 * N_DIM + c) = v0;
            *(float2*)(y + (size_t)(r0 + 8) * N_DIM + c) = v1;
        }
    }
}

// ---------------- launch ----------------

extern "C" void kernel_launch(void* const* d_in, const int* in_sizes, int n_in,
                              void* d_out, int out_size) {
    const float* x  = (const float*)d_in[0];
    const void*  w  = d_in[1];
    const float* ws = (const float*)d_in[2];
    float*       y  = (float*)d_out;

    const int M = in_sizes[0] / K_DIM;   // 16384

    cudaFuncSetAttribute(LinearDSV3_gemm,
                         cudaFuncAttributeMaxDynamicSharedMemorySize, SMEM_BYTES);

    LinearDSV3_prep<<<(N_DIM * K_DIM) / 1024, 256>>>(w);
    LinearDSV3_gemm<<<M / BM, THREADS, SMEM_BYTES>>>(x, ws, y);
}